// round 9
// baseline (speedup 1.0000x reference)
#include <cuda_runtime.h>
#include <math.h>

// GibbsSampler — round 9: big chunks + merged stamp/state word.
//
// 2 sweeps x 65536 sequential Potts updates in perm order. Chunks of 4096
// scan positions (4 per thread); conflicts (Chebyshev <= 1) execute in
// dependency waves. Cell state word W[cell] = [epoch:2|chunkpos:12|X:2]
// merges the dependency stamp and the lattice value: one LDS per neighbor
// serves both dep detection and value read. Epoch tagging removes stamp
// clears; stale epoch-aliased stamps only ADD wait constraints (benign,
// acyclic => no deadlock; min pending position is always ready => progress).
//
// Numerics: bit-exact round-7/8 pipeline (double-precision exp table, _rn
// mul/sub/add/div, sequential cumsum). OUTPUT IS FLOAT32.

#define NSITES 65536
#define NSWEEPS 2
#define BLOCK   1024
#define KPOS    4
#define CHUNK   (BLOCK * KPOS)       // 4096
#define NCHUNK  (NSITES / CHUNK)     // 16

__global__ __launch_bounds__(BLOCK, 1)
void gibbs_wave4(const unsigned int* __restrict__ A,   // X_init or perm
                 const unsigned int* __restrict__ B,   // the other one
                 const float* __restrict__ U,          // uniforms (2,65536)
                 const unsigned int* __restrict__ s0,  // beta or K
                 const unsigned int* __restrict__ s1,  // the other one
                 float* __restrict__ out)              // FLOAT32 output
{
    extern __shared__ unsigned char dyn[];
    unsigned short* W    = (unsigned short*)dyn;        // 131072 B
    unsigned char*  done = dyn + 131072;                // 4096 B

    __shared__ float4       s_B[729];
    __shared__ unsigned int s_maxA, s_maxB;

    const int tid = threadIdx.x;

    // ---------- classify the two 65536-int arrays (X_init max <= 3) ----------
    if (tid == 0) { s_maxA = 0u; s_maxB = 0u; }
    __syncthreads();
    {
        const uint4* A4 = (const uint4*)A;
        const uint4* B4 = (const uint4*)B;
        unsigned int mA = 0u, mB = 0u;
        for (int i = tid; i < NSITES / 4; i += BLOCK) {
            uint4 a = __ldg(&A4[i]);
            uint4 b = __ldg(&B4[i]);
            mA = max(max(max(a.x, a.y), max(a.z, a.w)), mA);
            mB = max(max(max(b.x, b.y), max(b.z, b.w)), mB);
        }
        atomicMax(&s_maxA, mA);
        atomicMax(&s_maxB, mB);
    }
    __syncthreads();
    const int b_is_x = (s_maxB <= 3u) && (s_maxA > 3u);
    const unsigned int* Xw = b_is_x ? B : A;
    const unsigned int* Pw = b_is_x ? A : B;

    // ---------- scalars: K low word == 4; beta f32 in [0.5,1.5) ----------
    const unsigned int w0 = __ldg(s0);
    const unsigned int w1 = __ldg(s1);
    float beta;
    if (w0 == 4u)      beta = __uint_as_float(w1);
    else if (w1 == 4u) beta = __uint_as_float(w0);
    else if (w0 >= 0x3F000000u && w0 < 0x3FC00000u) beta = __uint_as_float(w0);
    else               beta = __uint_as_float(w1);

    // ---------- init W: sentinel stamp (epoch 3, pos 4095 => never a dep) ----------
    for (int i = tid; i < NSITES; i += BLOCK)
        W[i] = (unsigned short)((3u << 14) | (4095u << 2) | (__ldg(&Xw[i]) & 3u));

    // ---------- boundary table (bit-exact): idx = c0 + 9*c1 + 81*c2 ----------
    for (int t = tid; t < 729; t += BLOCK) {
        int c0 = t % 9, c1 = (t / 9) % 9, c2 = t / 81;
        int c3 = 8 - c0 - c1 - c2;
        if (c3 >= 0) {
            int cm = max(max(c0, c1), max(c2, c3));
            float bm = __fmul_rn(beta, (float)cm);
            float e0 = (float)exp((double)__fsub_rn(__fmul_rn(beta, (float)c0), bm));
            float e1 = (float)exp((double)__fsub_rn(__fmul_rn(beta, (float)c1), bm));
            float e2 = (float)exp((double)__fsub_rn(__fmul_rn(beta, (float)c2), bm));
            float e3 = (float)exp((double)__fsub_rn(__fmul_rn(beta, (float)c3), bm));
            float s  = __fadd_rn(__fadd_rn(__fadd_rn(e0, e1), e2), e3);
            float a0 = __fdiv_rn(e0, s);
            float a1 = __fadd_rn(a0, __fdiv_rn(e1, s));
            float a2 = __fadd_rn(a1, __fdiv_rn(e2, s));
            float a3 = __fadd_rn(a2, __fdiv_rn(e3, s));
            s_B[t] = make_float4(a0, a1, a2, a3);
        }
    }
    __syncthreads();

    // ---------- sweeps: 4096-position chunks, dependency waves ----------
    for (int sweep = 0; sweep < NSWEEPS; sweep++) {
        const float* rs = U + sweep * NSITES;
        for (int chunk = 0; chunk < NCHUNK; chunk++) {
            const int base = chunk * CHUNK;
            const unsigned int ep = (unsigned int)((sweep * NCHUNK + chunk) & 3);

            int   site[KPOS];
            float rr[KPOS];
            #pragma unroll
            for (int k = 0; k < KPOS; k++) {
                int g = base + tid + k * BLOCK;
                site[k] = (int)(__ldg(&Pw[g]) & 0xFFFFu);
                rr[k]   = __ldg(&rs[g]);
            }

            // stamp own cells (RMW preserving X bits) + clear done flags
            #pragma unroll
            for (int k = 0; k < KPOS; k++) {
                int cp = tid + k * BLOCK;
                unsigned short w = W[site[k]];
                W[site[k]] = (unsigned short)((ep << 14) | ((unsigned)cp << 2) | (w & 3u));
                done[cp] = 0;
            }
            __syncthreads();

            unsigned int pend = (1u << KPOS) - 1u;
            int idx[KPOS];

            for (;;) {
                unsigned int ready = 0u;
                #pragma unroll
                for (int k = 0; k < KPOS; k++) {
                    if (!(pend & (1u << k))) continue;
                    const int s  = site[k];
                    const int cp = tid + k * BLOCK;
                    const int u = s >> 8, v = s & 255;
                    const int um = (u > 0)   ? u - 1 : 0;
                    const int up = (u < 255) ? u + 1 : 255;
                    const int vm = (v > 0)   ? v - 1 : 0;
                    const int vp = (v < 255) ? v + 1 : 255;
                    const int ra = um << 8, rb = u << 8, rc = up << 8;
                    unsigned int nw[8];
                    nw[0] = W[ra | vm]; nw[1] = W[ra | v]; nw[2] = W[ra | vp];
                    nw[3] = W[rb | vm];                    nw[4] = W[rb | vp];
                    nw[5] = W[rc | vm]; nw[6] = W[rc | v]; nw[7] = W[rc | vp];
                    int ok = 1;
                    int c0 = 0, c1 = 0, c2 = 0;
                    #pragma unroll
                    for (int j = 0; j < 8; j++) {
                        unsigned int wj = nw[j];
                        int x = (int)(wj & 3u);
                        c0 += (x == 0); c1 += (x == 1); c2 += (x == 2);
                        if ((wj >> 14) == ep) {
                            int pj = (int)((wj >> 2) & 0xFFFu);
                            if (pj < cp) ok &= (int)done[pj];
                        }
                    }
                    idx[k] = c0 + 9 * c1 + 81 * c2;
                    if (ok) ready |= (1u << k);
                }
                __syncthreads();   // reads above complete before writes below
                #pragma unroll
                for (int k = 0; k < KPOS; k++) {
                    if (!(ready & (1u << k))) continue;
                    const int cp = tid + k * BLOCK;
                    float4 b = s_B[idx[k]];
                    float r = rr[k];
                    int x = (b.x < r) + (b.y < r) + (b.z < r) + (b.w < r);
                    W[site[k]] = (unsigned short)((ep << 14) | ((unsigned)cp << 2) | (unsigned)x);
                    done[cp] = 1;
                    pend &= ~(1u << k);
                }
                if (__syncthreads_count(pend != 0u) == 0) break;
            }
        }
    }

    // ---------- FLOAT32 output ----------
    for (int i = tid; i < NSITES; i += BLOCK)
        out[i] = (float)(W[i] & 3u);
}

extern "C" void kernel_launch(void* const* d_in, const int* in_sizes, int n_in,
                              void* d_out, int out_size)
{
    // element-count mapping: 131072 -> uniforms; 65536 x2 -> X_init/perm; 1 -> scalars
    const void* arr64k[2] = {0, 0}; int n64k = 0;
    const void* scal[2]   = {0, 0}; int nsc = 0;
    const void* unif = 0;
    for (int i = 0; i < n_in; i++) {
        int s = in_sizes[i];
        if (s == 131072) unif = d_in[i];
        else if (s == 65536) { if (n64k < 2) arr64k[n64k++] = d_in[i]; }
        else if (s == 1)     { if (nsc  < 2) scal[nsc++]   = d_in[i]; }
    }
    if (!unif || n64k < 2 || nsc < 1) {
        // positional fallback: X_init, perm, uniforms, beta, K
        arr64k[0] = d_in[0];
        arr64k[1] = (n_in > 1) ? d_in[1] : d_in[0];
        unif      = (n_in > 2) ? d_in[2] : d_in[0];
        scal[0]   = (n_in > 3) ? d_in[3] : d_in[0];
        scal[1]   = (n_in > 4) ? d_in[4] : scal[0];
    }
    if (!scal[1]) scal[1] = scal[0];

    const size_t dyn_bytes = 131072 + 4096;   // W + done
    cudaFuncSetAttribute(gibbs_wave4,
                         cudaFuncAttributeMaxDynamicSharedMemorySize,
                         (int)dyn_bytes);
    gibbs_wave4<<<1, BLOCK, dyn_bytes>>>((const unsigned int*)arr64k[0],
                                         (const unsigned int*)arr64k[1],
                                         (const float*)unif,
                                         (const unsigned int*)scal[0],
                                         (const unsigned int*)scal[1],
                                         (float*)d_out);
}

// round 10
// speedup vs baseline: 1.0719x; 1.0719x over previous
#include <cuda_runtime.h>
#include <math.h>

// GibbsSampler — round 10: ASYNC dependency scheduling (no block-wide waves).
//
// 2 sweeps x 65536 sequential Potts updates in perm order. Chunks of 4096
// positions (4 per thread). After one stamp barrier, threads proceed fully
// asynchronously: an update waits (spin on volatile done flags) only for
// earlier-position updates stamped inside its clipped 3x3 box.
// Correctness: conflicts are symmetric (Chebyshev <= 1), so any adjacent
// later-position writer is itself blocked on OUR done flag => neighbor values
// are stable unless the neighbor is an earlier-position dep, which we spin on
// and re-read after an acquire fence. Release fence before setting done.
// Wait-for edges point to strictly smaller scan positions => acyclic => no
// deadlock (ITS schedules spinning lanes fairly on sm_103a).
//
// Numerics: bit-exact pipeline from rounds 7-9 (double-precision exp table,
// _rn mul/sub/add/div, sequential cumsum). OUTPUT IS FLOAT32.

#define NSITES 65536
#define NSWEEPS 2
#define BLOCK   1024
#define KPOS    4
#define CHUNK   (BLOCK * KPOS)       // 4096
#define NCHUNK  (NSITES / CHUNK)     // 16
#define SENT    0x3FFFu              // sentinel stamp position (never < cp)

__global__ __launch_bounds__(BLOCK, 1)
void gibbs_async(const unsigned int* __restrict__ A,   // X_init or perm
                 const unsigned int* __restrict__ B,   // the other one
                 const float* __restrict__ U,          // uniforms (2,65536)
                 const unsigned int* __restrict__ s0,  // beta or K
                 const unsigned int* __restrict__ s1,  // the other one
                 float* __restrict__ out)              // FLOAT32 output
{
    extern __shared__ unsigned char dyn[];
    unsigned short* W    = (unsigned short*)dyn;            // 131072 B: [pos:14|X:2]
    unsigned int*   done = (unsigned int*)(dyn + 131072);   // 16384 B
    volatile unsigned int*   vdone = done;
    volatile unsigned short* vW    = W;

    __shared__ float4       s_B[729];
    __shared__ unsigned int s_maxA, s_maxB;

    const int tid = threadIdx.x;

    // ---------- classify the two 65536-int arrays (X_init max <= 3) ----------
    if (tid == 0) { s_maxA = 0u; s_maxB = 0u; }
    __syncthreads();
    {
        const uint4* A4 = (const uint4*)A;
        const uint4* B4 = (const uint4*)B;
        unsigned int mA = 0u, mB = 0u;
        for (int i = tid; i < NSITES / 4; i += BLOCK) {
            uint4 a = __ldg(&A4[i]);
            uint4 b = __ldg(&B4[i]);
            mA = max(max(max(a.x, a.y), max(a.z, a.w)), mA);
            mB = max(max(max(b.x, b.y), max(b.z, b.w)), mB);
        }
        atomicMax(&s_maxA, mA);
        atomicMax(&s_maxB, mB);
    }
    __syncthreads();
    const int b_is_x = (s_maxB <= 3u) && (s_maxA > 3u);
    const unsigned int* Xw = b_is_x ? B : A;
    const unsigned int* Pw = b_is_x ? A : B;

    // ---------- scalars: K low word == 4; beta f32 in [0.5,1.5) ----------
    const unsigned int w0 = __ldg(s0);
    const unsigned int w1 = __ldg(s1);
    float beta;
    if (w0 == 4u)      beta = __uint_as_float(w1);
    else if (w1 == 4u) beta = __uint_as_float(w0);
    else if (w0 >= 0x3F000000u && w0 < 0x3FC00000u) beta = __uint_as_float(w0);
    else               beta = __uint_as_float(w1);

    // ---------- init W with sentinel stamps ----------
    for (int i = tid; i < NSITES; i += BLOCK)
        W[i] = (unsigned short)((SENT << 2) | (__ldg(&Xw[i]) & 3u));

    // ---------- boundary table (bit-exact): idx = c0 + 9*c1 + 81*c2 ----------
    for (int t = tid; t < 729; t += BLOCK) {
        int c0 = t % 9, c1 = (t / 9) % 9, c2 = t / 81;
        int c3 = 8 - c0 - c1 - c2;
        if (c3 >= 0) {
            int cm = max(max(c0, c1), max(c2, c3));
            float bm = __fmul_rn(beta, (float)cm);
            float e0 = (float)exp((double)__fsub_rn(__fmul_rn(beta, (float)c0), bm));
            float e1 = (float)exp((double)__fsub_rn(__fmul_rn(beta, (float)c1), bm));
            float e2 = (float)exp((double)__fsub_rn(__fmul_rn(beta, (float)c2), bm));
            float e3 = (float)exp((double)__fsub_rn(__fmul_rn(beta, (float)c3), bm));
            float s  = __fadd_rn(__fadd_rn(__fadd_rn(e0, e1), e2), e3);
            float a0 = __fdiv_rn(e0, s);
            float a1 = __fadd_rn(a0, __fdiv_rn(e1, s));
            float a2 = __fadd_rn(a1, __fdiv_rn(e2, s));
            float a3 = __fadd_rn(a2, __fdiv_rn(e3, s));
            s_B[t] = make_float4(a0, a1, a2, a3);
        }
    }
    __syncthreads();

    // ---------- sweeps: 4096-position chunks, async dep scheduling ----------
    for (int sweep = 0; sweep < NSWEEPS; sweep++) {
        const float* rs = U + sweep * NSITES;
        for (int chunk = 0; chunk < NCHUNK; chunk++) {
            const int base = chunk * CHUNK;

            int   site[KPOS];
            float rr[KPOS];
            #pragma unroll
            for (int k = 0; k < KPOS; k++) {
                int g = base + tid + k * BLOCK;
                site[k] = (int)(__ldg(&Pw[g]) & 0xFFFFu);
                rr[k]   = __ldg(&rs[g]);
            }

            // ---- stamp phase ----
            #pragma unroll
            for (int k = 0; k < KPOS; k++) {
                int cp = tid + k * BLOCK;
                unsigned short w = W[site[k]];
                W[site[k]] = (unsigned short)(((unsigned)cp << 2) | (w & 3u));
                done[cp] = 0u;
            }
            __syncthreads();

            // ---- async execution, own positions in ascending order ----
            #pragma unroll
            for (int k = 0; k < KPOS; k++) {
                const int cp = tid + k * BLOCK;
                const int s  = site[k];
                const int u = s >> 8, v = s & 255;
                const int um = (u > 0)   ? u - 1 : 0;
                const int up = (u < 255) ? u + 1 : 255;
                const int vm = (v > 0)   ? v - 1 : 0;
                const int vp = (v < 255) ? v + 1 : 255;
                const int ra = um << 8, rb = u << 8, rc = up << 8;
                int na[8];
                na[0] = ra | vm; na[1] = ra | v; na[2] = ra | vp;
                na[3] = rb | vm;                 na[4] = rb | vp;
                na[5] = rc | vm; na[6] = rc | v; na[7] = rc | vp;

                unsigned int acc = 0u;   // byte-packed counts of classes 0..2
                #pragma unroll
                for (int j = 0; j < 8; j++) {
                    unsigned int wj = W[na[j]];
                    int pos = (int)(wj >> 2);
                    if (pos < cp) {                  // earlier-position dep
                        while (vdone[pos] == 0u) { } // spin (ITS-fair)
                        __threadfence_block();       // acquire
                        wj = vW[na[j]];              // fresh value
                    }
                    acc += 1u << ((wj & 3u) * 8u);
                }
                int c0 = (int)(acc & 0xFFu);
                int c1 = (int)((acc >> 8) & 0xFFu);
                int c2 = (int)((acc >> 16) & 0xFFu);
                float4 b = s_B[c0 + 9 * c1 + 81 * c2];
                float r = rr[k];
                int x = (b.x < r) + (b.y < r) + (b.z < r) + (b.w < r);
                W[s] = (unsigned short)(((unsigned)cp << 2) | (unsigned)x);
                __threadfence_block();               // release
                vdone[cp] = 1u;
            }
            __syncthreads();

            // ---- clear stamps back to sentinel (values preserved) ----
            #pragma unroll
            for (int k = 0; k < KPOS; k++) {
                unsigned short w = W[site[k]];
                W[site[k]] = (unsigned short)((SENT << 2) | (w & 3u));
            }
            __syncthreads();
        }
    }

    // ---------- FLOAT32 output ----------
    for (int i = tid; i < NSITES; i += BLOCK)
        out[i] = (float)(W[i] & 3u);
}

extern "C" void kernel_launch(void* const* d_in, const int* in_sizes, int n_in,
                              void* d_out, int out_size)
{
    // element-count mapping: 131072 -> uniforms; 65536 x2 -> X_init/perm; 1 -> scalars
    const void* arr64k[2] = {0, 0}; int n64k = 0;
    const void* scal[2]   = {0, 0}; int nsc = 0;
    const void* unif = 0;
    for (int i = 0; i < n_in; i++) {
        int s = in_sizes[i];
        if (s == 131072) unif = d_in[i];
        else if (s == 65536) { if (n64k < 2) arr64k[n64k++] = d_in[i]; }
        else if (s == 1)     { if (nsc  < 2) scal[nsc++]   = d_in[i]; }
    }
    if (!unif || n64k < 2 || nsc < 1) {
        // positional fallback: X_init, perm, uniforms, beta, K
        arr64k[0] = d_in[0];
        arr64k[1] = (n_in > 1) ? d_in[1] : d_in[0];
        unif      = (n_in > 2) ? d_in[2] : d_in[0];
        scal[0]   = (n_in > 3) ? d_in[3] : d_in[0];
        scal[1]   = (n_in > 4) ? d_in[4] : scal[0];
    }
    if (!scal[1]) scal[1] = scal[0];

    const size_t dyn_bytes = 131072 + 16384;   // W + done
    cudaFuncSetAttribute(gibbs_async,
                         cudaFuncAttributeMaxDynamicSharedMemorySize,
                         (int)dyn_bytes);
    gibbs_async<<<1, BLOCK, dyn_bytes>>>((const unsigned int*)arr64k[0],
                                         (const unsigned int*)arr64k[1],
                                         (const float*)unif,
                                         (const unsigned int*)scal[0],
                                         (const unsigned int*)scal[1],
                                         (float*)d_out);
}

// round 11
// speedup vs baseline: 2.8197x; 2.6305x over previous
#include <cuda_runtime.h>
#include <math.h>

// GibbsSampler — round 11: precomputed level schedule + lean wave execution.
//
// The wave schedule (level of each scan position within its 1024-chunk)
// depends ONLY on perm, which is identical for both sweeps. Phase 1 computes
// levels once via a monotone fixpoint (conflict = Chebyshev <= 1 via a stamp
// grid; level(i) = 1 + max level of earlier conflicting positions). Phase 2
// executes both sweeps: wave w updates exactly the positions with level w,
// one __syncthreads per wave — no stamps, no done flags, no spinning.
// Correctness: conflicting pairs get strictly ordered levels (=> scan order
// respected, reads of later-conflicting sites see pre-update values);
// same-level updates are mutually non-conflicting => disjoint read/write sets.
//
// Numerics: bit-exact pipeline from rounds 7-10 (double-precision exp table,
// _rn mul/sub/add/div, sequential cumsum). OUTPUT IS FLOAT32.

#define NSITES 65536
#define NSWEEPS 2
#define BLOCK   1024
#define NCHUNK  (NSITES / BLOCK)     // 64 chunks per sweep

__global__ __launch_bounds__(BLOCK, 1)
void gibbs_sched(const unsigned int* __restrict__ A,   // X_init or perm
                 const unsigned int* __restrict__ B,   // the other one
                 const float* __restrict__ U,          // uniforms (2,65536)
                 const unsigned int* __restrict__ s0,  // beta or K
                 const unsigned int* __restrict__ s1,  // the other one
                 float* __restrict__ out)              // FLOAT32 output
{
    extern __shared__ unsigned char dyn[];
    unsigned short* stamp = (unsigned short*)dyn;      // [0,131072): scheduling only
    unsigned char*  Xs    = dyn;                       // overlays stamp after phase 1
    unsigned char*  lvl   = dyn + 131072;              // [131072,196608): u8 level/pos

    __shared__ float4       s_B[729];
    __shared__ int          s_cmax[NCHUNK];
    __shared__ unsigned int s_maxA, s_maxB;

    const int tid = threadIdx.x;

    // ---------- classify inputs ----------
    if (tid == 0) { s_maxA = 0u; s_maxB = 0u; }
    if (tid < NCHUNK) s_cmax[tid] = 0;
    __syncthreads();
    {
        const uint4* A4 = (const uint4*)A;
        const uint4* B4 = (const uint4*)B;
        unsigned int mA = 0u, mB = 0u;
        for (int i = tid; i < NSITES / 4; i += BLOCK) {
            uint4 a = __ldg(&A4[i]);
            uint4 b = __ldg(&B4[i]);
            mA = max(max(max(a.x, a.y), max(a.z, a.w)), mA);
            mB = max(max(max(b.x, b.y), max(b.z, b.w)), mB);
        }
        atomicMax(&s_maxA, mA);
        atomicMax(&s_maxB, mB);
    }
    __syncthreads();
    const int b_is_x = (s_maxB <= 3u) && (s_maxA > 3u);
    const unsigned int* Xw = b_is_x ? B : A;
    const unsigned int* Pw = b_is_x ? A : B;

    const unsigned int w0 = __ldg(s0);
    const unsigned int w1 = __ldg(s1);
    float beta;
    if (w0 == 4u)      beta = __uint_as_float(w1);
    else if (w1 == 4u) beta = __uint_as_float(w0);
    else if (w0 >= 0x3F000000u && w0 < 0x3FC00000u) beta = __uint_as_float(w0);
    else               beta = __uint_as_float(w1);

    // ---------- boundary table (bit-exact) + stamp init ----------
    for (int i = tid; i < NSITES; i += BLOCK) stamp[i] = 0xFFFFu;
    for (int t = tid; t < 729; t += BLOCK) {
        int c0 = t % 9, c1 = (t / 9) % 9, c2 = t / 81;
        int c3 = 8 - c0 - c1 - c2;
        if (c3 >= 0) {
            int cm = max(max(c0, c1), max(c2, c3));
            float bm = __fmul_rn(beta, (float)cm);
            float e0 = (float)exp((double)__fsub_rn(__fmul_rn(beta, (float)c0), bm));
            float e1 = (float)exp((double)__fsub_rn(__fmul_rn(beta, (float)c1), bm));
            float e2 = (float)exp((double)__fsub_rn(__fmul_rn(beta, (float)c2), bm));
            float e3 = (float)exp((double)__fsub_rn(__fmul_rn(beta, (float)c3), bm));
            float s  = __fadd_rn(__fadd_rn(__fadd_rn(e0, e1), e2), e3);
            float a0 = __fdiv_rn(e0, s);
            float a1 = __fadd_rn(a0, __fdiv_rn(e1, s));
            float a2 = __fadd_rn(a1, __fdiv_rn(e2, s));
            float a3 = __fadd_rn(a2, __fdiv_rn(e3, s));
            s_B[t] = make_float4(a0, a1, a2, a3);
        }
    }
    __syncthreads();

    // ---------- PHASE 1: compute level schedule (valid for BOTH sweeps) ----------
    for (int chunk = 0; chunk < NCHUNK; chunk++) {
        const int base = chunk << 10;
        const int site = (int)(__ldg(&Pw[base + tid]) & 0xFFFFu);
        const int u = site >> 8, v = site & 255;

        stamp[site] = (unsigned short)tid;
        __syncthreads();

        const int um = (u > 0)   ? u - 1 : 0;
        const int up = (u < 255) ? u + 1 : 255;
        const int vm = (v > 0)   ? v - 1 : 0;
        const int vp = (v < 255) ? v + 1 : 255;
        const int ra = um << 8, rb = u << 8, rc = up << 8;

        int d0 = (int)stamp[ra | vm], d1 = (int)stamp[ra | v];
        int d2 = (int)stamp[ra | vp], d3 = (int)stamp[rb | vm];
        int d4 = (int)stamp[rb | vp], d5 = (int)stamp[rc | vm];
        int d6 = (int)stamp[rc | v],  d7 = (int)stamp[rc | vp];
        if (d0 >= tid) d0 = -1;  if (d1 >= tid) d1 = -1;
        if (d2 >= tid) d2 = -1;  if (d3 >= tid) d3 = -1;
        if (d4 >= tid) d4 = -1;  if (d5 >= tid) d5 = -1;
        if (d6 >= tid) d6 = -1;  if (d7 >= tid) d7 = -1;
        __syncthreads();                 // all stamp reads done
        stamp[site] = 0xFFFFu;           // clear for next chunk

        const int ndep = (d0 >= 0) + (d1 >= 0) + (d2 >= 0) + (d3 >= 0) +
                         (d4 >= 0) + (d5 >= 0) + (d6 >= 0) + (d7 >= 0);
        int myl = (ndep == 0) ? 1 : 0;
        lvl[base + tid] = (unsigned char)myl;
        __syncthreads();                 // inits visible before fixpoint reads

        // monotone fixpoint: u8 level writes are atomic; a stale-0 read only
        // delays a thread to the next iteration (levels set 0 -> final once).
        for (;;) {
            if (!myl) {
                int ok = 1, mx = 0, l;
                if (d0 >= 0) { l = (int)lvl[base + d0]; ok &= (l != 0); mx = max(mx, l); }
                if (d1 >= 0) { l = (int)lvl[base + d1]; ok &= (l != 0); mx = max(mx, l); }
                if (d2 >= 0) { l = (int)lvl[base + d2]; ok &= (l != 0); mx = max(mx, l); }
                if (d3 >= 0) { l = (int)lvl[base + d3]; ok &= (l != 0); mx = max(mx, l); }
                if (d4 >= 0) { l = (int)lvl[base + d4]; ok &= (l != 0); mx = max(mx, l); }
                if (d5 >= 0) { l = (int)lvl[base + d5]; ok &= (l != 0); mx = max(mx, l); }
                if (d6 >= 0) { l = (int)lvl[base + d6]; ok &= (l != 0); mx = max(mx, l); }
                if (d7 >= 0) { l = (int)lvl[base + d7]; ok &= (l != 0); mx = max(mx, l); }
                if (ok) { myl = mx + 1; lvl[base + tid] = (unsigned char)myl; }
            }
            if (__syncthreads_count(myl == 0) == 0) break;
        }

        int wmax = __reduce_max_sync(0xFFFFFFFFu, myl);
        if ((tid & 31) == 0) atomicMax(&s_cmax[chunk], wmax);
    }
    __syncthreads();

    // ---------- load lattice (overlays the no-longer-needed stamp region) ----------
    for (int i = tid; i < NSITES; i += BLOCK)
        Xs[i] = (unsigned char)(__ldg(&Xw[i]) & 3u);
    __syncthreads();

    // ---------- PHASE 2: execute both sweeps on the precomputed schedule ----------
    for (int sweep = 0; sweep < NSWEEPS; sweep++) {
        const float* rs = U + sweep * NSITES;
        for (int chunk = 0; chunk < NCHUNK; chunk++) {
            const int base = chunk << 10;
            const int site = (int)(__ldg(&Pw[base + tid]) & 0xFFFFu);
            const float r  = __ldg(&rs[base + tid]);
            const int  myl = (int)lvl[base + tid];
            const int cmax = s_cmax[chunk];

            const int u = site >> 8, v = site & 255;
            const int um = (u > 0)   ? u - 1 : 0;
            const int up = (u < 255) ? u + 1 : 255;
            const int vm = (v > 0)   ? v - 1 : 0;
            const int vp = (v < 255) ? v + 1 : 255;
            const int ra = um << 8, rb = u << 8, rc = up << 8;

            for (int w = 1; w <= cmax; w++) {
                if (myl == w) {
                    unsigned int acc = 0u;       // byte-packed counts, classes 0-2
                    acc += 1u << (((unsigned)Xs[ra | vm] & 3u) * 8u);
                    acc += 1u << (((unsigned)Xs[ra | v ] & 3u) * 8u);
                    acc += 1u << (((unsigned)Xs[ra | vp] & 3u) * 8u);
                    acc += 1u << (((unsigned)Xs[rb | vm] & 3u) * 8u);
                    acc += 1u << (((unsigned)Xs[rb | vp] & 3u) * 8u);
                    acc += 1u << (((unsigned)Xs[rc | vm] & 3u) * 8u);
                    acc += 1u << (((unsigned)Xs[rc | v ] & 3u) * 8u);
                    acc += 1u << (((unsigned)Xs[rc | vp] & 3u) * 8u);
                    int c0 = (int)(acc & 0xFFu);
                    int c1 = (int)((acc >> 8) & 0xFFu);
                    int c2 = (int)((acc >> 16) & 0xFFu);
                    float4 b = s_B[c0 + 9 * c1 + 81 * c2];
                    int x = (b.x < r) + (b.y < r) + (b.z < r) + (b.w < r);
                    Xs[site] = (unsigned char)x;
                }
                __syncthreads();   // wave w writes before wave w+1 reads
            }
        }
    }

    // ---------- FLOAT32 output ----------
    for (int i = tid; i < NSITES; i += BLOCK)
        out[i] = (float)Xs[i];
}

extern "C" void kernel_launch(void* const* d_in, const int* in_sizes, int n_in,
                              void* d_out, int out_size)
{
    // element-count mapping: 131072 -> uniforms; 65536 x2 -> X_init/perm; 1 -> scalars
    const void* arr64k[2] = {0, 0}; int n64k = 0;
    const void* scal[2]   = {0, 0}; int nsc = 0;
    const void* unif = 0;
    for (int i = 0; i < n_in; i++) {
        int s = in_sizes[i];
        if (s == 131072) unif = d_in[i];
        else if (s == 65536) { if (n64k < 2) arr64k[n64k++] = d_in[i]; }
        else if (s == 1)     { if (nsc  < 2) scal[nsc++]   = d_in[i]; }
    }
    if (!unif || n64k < 2 || nsc < 1) {
        // positional fallback: X_init, perm, uniforms, beta, K
        arr64k[0] = d_in[0];
        arr64k[1] = (n_in > 1) ? d_in[1] : d_in[0];
        unif      = (n_in > 2) ? d_in[2] : d_in[0];
        scal[0]   = (n_in > 3) ? d_in[3] : d_in[0];
        scal[1]   = (n_in > 4) ? d_in[4] : scal[0];
    }
    if (!scal[1]) scal[1] = scal[0];

    const size_t dyn_bytes = 131072 + 65536;   // stamp/X overlay + lvl
    cudaFuncSetAttribute(gibbs_sched,
                         cudaFuncAttributeMaxDynamicSharedMemorySize,
                         (int)dyn_bytes);
    gibbs_sched<<<1, BLOCK, dyn_bytes>>>((const unsigned int*)arr64k[0],
                                         (const unsigned int*)arr64k[1],
                                         (const float*)unif,
                                         (const unsigned int*)scal[0],
                                         (const unsigned int*)scal[1],
                                         (float*)d_out);
}